// round 12
// baseline (speedup 1.0000x reference)
#include <cuda_runtime.h>

#define T_STEPS 2048
#define B_SIZE  4096
#define OUTD    4
#define D_SEG   8
#define NSEG    (T_STEPS / D_SEG)   // 256

typedef unsigned long long u64;

// ---------- packed f32x2 helpers (sm_100a) ----------
__device__ __forceinline__ u64 pack2(float lo, float hi) {
    u64 r;
    asm("mov.b64 %0, {%1, %2};"
        : "=l"(r) : "r"(__float_as_uint(lo)), "r"(__float_as_uint(hi)));
    return r;
}
__device__ __forceinline__ float hadd2(u64 v) {
    unsigned a, b;
    asm("mov.b64 {%0, %1}, %2;" : "=r"(a), "=r"(b) : "l"(v));
    return __uint_as_float(a) + __uint_as_float(b);
}
__device__ __forceinline__ u64 fma2(u64 a, u64 b, u64 c) {
    u64 d;
    asm("fma.rn.f32x2 %0, %1, %2, %3;" : "=l"(d) : "l"(a), "l"(b), "l"(c));
    return d;
}
__device__ __forceinline__ u64 add2(u64 a, u64 b) {
    u64 d;
    asm("add.rn.f32x2 %0, %1, %2;" : "=l"(d) : "l"(a), "l"(b));
    return d;
}
__device__ __forceinline__ float tanh_mufu(float x) {
    float r; asm("tanh.approx.f32 %0, %1;" : "=f"(r) : "f"(x)); return r;
}

// tree-shaped packed dot over 8 (4 pairs), zero seed; horizontal sum
__device__ __forceinline__ float dot8z(const u64 (&w)[4], const u64 (&p)[4]) {
    u64 a = fma2(w[0], p[0], 0ULL);
    u64 b = fma2(w[1], p[1], 0ULL);
    a = fma2(w[2], p[2], a);
    b = fma2(w[3], p[3], b);
    return hadd2(add2(a, b));
}

// named barriers, 64 threads (one producer warp + one consumer warp)
#define BAR_SYNC(id)   asm volatile("bar.sync %0, 64;"   :: "r"(id) : "memory")
#define BAR_ARRIVE(id) asm volatile("bar.arrive %0, 64;" :: "r"(id) : "memory")
// ids: FULL01 = 1+p, FREE01 = 3+p, FULL12 = 5+p, FREE12 = 7+p  (p = parity)

// 3 warps/block: warp L owns GRU layer L. Depth-8 segmented pipeline with
// per-parity producer/consumer named barriers (no block-wide lockstep).
// 4 batch elements per block (8 lanes each).
__global__ void __launch_bounds__(96, 7)
gru3_pipe_kernel(const float* __restrict__ x,
                 const float* __restrict__ Wih0, const float* __restrict__ Whh0,
                 const float* __restrict__ bih0, const float* __restrict__ bhh0,
                 const float* __restrict__ Wih1, const float* __restrict__ Whh1,
                 const float* __restrict__ bih1, const float* __restrict__ bhh1,
                 const float* __restrict__ Wih2, const float* __restrict__ Whh2,
                 const float* __restrict__ bih2, const float* __restrict__ bhh2,
                 const float* __restrict__ fcW,  const float* __restrict__ fcb,
                 float* __restrict__ out)
{
    const int wid  = threadIdx.x >> 5;   // layer id 0..2
    const int lane = threadIdx.x & 31;
    const int e    = lane >> 3;          // element within block (0..3)
    const int sub  = lane & 7;           // hidden unit
    const int b    = blockIdx.x * 4 + e; // global batch element

    // [parity][slot-in-segment][lane]
    __shared__ __align__(16) float h0buf[2][D_SEG][32];
    __shared__ __align__(16) float h1buf[2][D_SEG][32];
    __shared__ __align__(16) float h2scr[32];      // warp-2 self-broadcast scratch

    if (wid == 0) {
        // ================= layer 0 (producer: x -> h0buf) =================
        u64 whh[3][4];
        float wxa[3], wxb[3];
        const float2* Whhv = (const float2*)Whh0;
#pragma unroll
        for (int gt = 0; gt < 3; gt++) {
            const int row = gt * 8 + sub;
            const float sih = (gt < 2) ? 0.5f : 1.0f;
#pragma unroll
            for (int kk = 0; kk < 4; kk++) {
                float2 a = Whhv[row * 4 + kk];
                whh[gt][kk] = pack2(0.5f * a.x, 0.5f * a.y);
            }
            wxa[gt] = sih * Wih0[row * 2 + 0];
            wxb[gt] = sih * Wih0[row * 2 + 1];
        }
        const float bR = 0.5f * (bih0[sub] + bhh0[sub]);
        const float bZ = 0.5f * (bih0[8 + sub] + bhh0[8 + sub]);
        const float bX = bih0[16 + sub];
        const float bH = 0.5f * bhh0[16 + sub];

        float h = 0.0f, rc = bR, zc = bZ, uc = bH;

        // cooperative x staging: lane (e_l*8 + d_l) holds x[t0+d_l, b(e_l)]
        const int dl = lane & 7, el = lane >> 3;
        const float* xg = x + ((size_t)dl * B_SIZE + (blockIdx.x * 4 + el)) * 2;
        float2 cur = __ldg((const float2*)xg);   // segment 0
        float2 nxt;

#pragma unroll 1
        for (int s = 0; s < NSEG; s++) {
            const int p = s & 1;
            if (s >= 2) BAR_SYNC(3 + p);         // FREE01_p: consumer done with this parity
            nxt = (s + 1 < NSEG)
                ? __ldg((const float2*)(xg + (size_t)(s + 1) * D_SEG * B_SIZE * 2))
                : cur;

#pragma unroll 1
            for (int d = 0; d < D_SEG; d++) {
                const int src = (lane & 24) | d;
                float xa = __shfl_sync(0xffffffffu, cur.x, src);
                float xc = __shfl_sync(0xffffffffu, cur.y, src);

                float aR = fmaf(wxa[0], xa, fmaf(wxb[0], xc, rc));
                float aZ = fmaf(wxa[1], xa, fmaf(wxb[1], xc, zc));
                float c  = fmaf(wxa[2], xa, fmaf(wxb[2], xc, uc + bX));
                float sr = tanh_mufu(aR);
                float sz = tanh_mufu(aZ);
                float n  = tanh_mufu(fmaf(sr, uc, c));
                float A  = 0.5f * h;
                h = fmaf(sz, fmaf(-0.5f, n, A), fmaf(0.5f, n, A));
                h0buf[p][d][lane] = h;

                // self-broadcast via smem readback (replaces 8x shfl)
                const u64* qp = (const u64*)&h0buf[p][d][e * 8];
                u64 Q[4] = {qp[0], qp[1], qp[2], qp[3]};
                rc = dot8z(whh[0], Q) + bR;
                zc = dot8z(whh[1], Q) + bZ;
                uc = dot8z(whh[2], Q) + bH;
            }
            cur = nxt;
            BAR_ARRIVE(1 + p);                   // FULL01_p: segment s ready
        }
    } else if (wid == 1) {
        // ========== layer 1 (consumer of h0buf, producer of h1buf) ==========
        u64 wih[3][4], whh[3][4];
        const float2* Wihv = (const float2*)Wih1;
        const float2* Whhv = (const float2*)Whh1;
#pragma unroll
        for (int gt = 0; gt < 3; gt++) {
            const int row = gt * 8 + sub;
            const float sih = (gt < 2) ? 0.5f : 1.0f;
#pragma unroll
            for (int kk = 0; kk < 4; kk++) {
                float2 a = Whhv[row * 4 + kk];
                whh[gt][kk] = pack2(0.5f * a.x, 0.5f * a.y);
                float2 d2 = Wihv[row * 4 + kk];
                wih[gt][kk] = pack2(sih * d2.x, sih * d2.y);
            }
        }
        const float bR = 0.5f * (bih1[sub] + bhh1[sub]);
        const float bZ = 0.5f * (bih1[8 + sub] + bhh1[8 + sub]);
        const float bX = bih1[16 + sub];
        const float bH = 0.5f * bhh1[16 + sub];

        float h = 0.0f, rc = bR, zc = bZ, uc = bH;

#pragma unroll 1
        for (int r = 0; r < NSEG; r++) {
            const int p = r & 1;
            BAR_SYNC(1 + p);                     // FULL01_p: h0 segment r ready
            if (r >= 2) BAR_SYNC(7 + p);         // FREE12_p: layer2 done with h1 parity
#pragma unroll 1
            for (int d = 0; d < D_SEG; d++) {
                const u64* pp = (const u64*)&h0buf[p][d][e * 8];
                u64 P[4] = {pp[0], pp[1], pp[2], pp[3]};

                float aR = dot8z(wih[0], P) + rc;
                float aZ = dot8z(wih[1], P) + zc;
                float c  = dot8z(wih[2], P) + (uc + bX);
                float sr = tanh_mufu(aR);
                float sz = tanh_mufu(aZ);
                float n  = tanh_mufu(fmaf(sr, uc, c));
                float A  = 0.5f * h;
                h = fmaf(sz, fmaf(-0.5f, n, A), fmaf(0.5f, n, A));
                h1buf[p][d][lane] = h;

                const u64* qp = (const u64*)&h1buf[p][d][e * 8];
                u64 Q[4] = {qp[0], qp[1], qp[2], qp[3]};
                rc = dot8z(whh[0], Q) + bR;
                zc = dot8z(whh[1], Q) + bZ;
                uc = dot8z(whh[2], Q) + bH;
            }
            BAR_ARRIVE(3 + p);                   // FREE01_p: done reading h0 parity
            BAR_ARRIVE(5 + p);                   // FULL12_p: h1 segment r ready
        }
    } else {
        // ================= layer 2 (consumer of h1buf) =================
        u64 wih[3][4], whh[3][4];
        const float2* Wihv = (const float2*)Wih2;
        const float2* Whhv = (const float2*)Whh2;
#pragma unroll
        for (int gt = 0; gt < 3; gt++) {
            const int row = gt * 8 + sub;
            const float sih = (gt < 2) ? 0.5f : 1.0f;
#pragma unroll
            for (int kk = 0; kk < 4; kk++) {
                float2 a = Whhv[row * 4 + kk];
                whh[gt][kk] = pack2(0.5f * a.x, 0.5f * a.y);
                float2 d2 = Wihv[row * 4 + kk];
                wih[gt][kk] = pack2(sih * d2.x, sih * d2.y);
            }
        }
        const float bR = 0.5f * (bih2[sub] + bhh2[sub]);
        const float bZ = 0.5f * (bih2[8 + sub] + bhh2[8 + sub]);
        const float bX = bih2[16 + sub];
        const float bH = 0.5f * bhh2[16 + sub];

        float h = 0.0f, rc = bR, zc = bZ, uc = bH, acc = 0.0f;

#pragma unroll 1
        for (int r = 0; r < NSEG; r++) {
            const int p = r & 1;
            BAR_SYNC(5 + p);                     // FULL12_p: h1 segment r ready
#pragma unroll 1
            for (int d = 0; d < D_SEG; d++) {
                const u64* pp = (const u64*)&h1buf[p][d][e * 8];
                u64 P[4] = {pp[0], pp[1], pp[2], pp[3]};

                float aR = dot8z(wih[0], P) + rc;
                float aZ = dot8z(wih[1], P) + zc;
                float c  = dot8z(wih[2], P) + (uc + bX);
                float sr = tanh_mufu(aR);
                float sz = tanh_mufu(aZ);
                float n  = tanh_mufu(fmaf(sr, uc, c));
                float A  = 0.5f * h;
                h = fmaf(sz, fmaf(-0.5f, n, A), fmaf(0.5f, n, A));
                acc += h;

                h2scr[lane] = h;                 // self-broadcast scratch
                const u64* qp = (const u64*)&h2scr[e * 8];
                u64 Q[4] = {qp[0], qp[1], qp[2], qp[3]};
                rc = dot8z(whh[0], Q) + bR;
                zc = dot8z(whh[1], Q) + bZ;
                uc = dot8z(whh[2], Q) + bH;
            }
            BAR_ARRIVE(7 + p);                   // FREE12_p: done reading h1 parity
        }

        // mean over T, then FC (OUT=4)
        const float mean = acc * (1.0f / (float)T_STEPS);
        float m[8];
#pragma unroll
        for (int k = 0; k < 8; k++)
            m[k] = __shfl_sync(0xffffffffu, mean, k, 8);
        if (sub < OUTD) {
            float o = __ldg(fcb + sub);
#pragma unroll
            for (int k = 0; k < 8; k++)
                o = fmaf(__ldg(fcW + sub * 8 + k), m[k], o);
            out[(size_t)b * OUTD + sub] = o;
        }
    }
}

extern "C" void kernel_launch(void* const* d_in, const int* in_sizes, int n_in,
                              void* d_out, int out_size)
{
    const float* x    = (const float*)d_in[0];
    const float* Wih0 = (const float*)d_in[1];
    const float* Whh0 = (const float*)d_in[2];
    const float* bih0 = (const float*)d_in[3];
    const float* bhh0 = (const float*)d_in[4];
    const float* Wih1 = (const float*)d_in[5];
    const float* Whh1 = (const float*)d_in[6];
    const float* bih1 = (const float*)d_in[7];
    const float* bhh1 = (const float*)d_in[8];
    const float* Wih2 = (const float*)d_in[9];
    const float* Whh2 = (const float*)d_in[10];
    const float* bih2 = (const float*)d_in[11];
    const float* bhh2 = (const float*)d_in[12];
    const float* fcW  = (const float*)d_in[13];
    const float* fcb  = (const float*)d_in[14];
    float* out = (float*)d_out;

    // 4 elements per block, 3 warps per block -> 1024 blocks
    gru3_pipe_kernel<<<B_SIZE / 4, 96>>>(
        x,
        Wih0, Whh0, bih0, bhh0,
        Wih1, Whh1, bih1, bhh1,
        Wih2, Whh2, bih2, bhh2,
        fcW, fcb, out);
}